// round 13
// baseline (speedup 1.0000x reference)
#include <cuda_runtime.h>
#include <cuda_fp16.h>
#include <cstdint>

// ============================================================
// Problem sizes (fixed per reference)
// ============================================================
#define B_S       8192          // GEMM M  (B*S = 4*2048)
#define IN_DIM    4096          // K
#define OUT_DIM   4096          // N
// GEMM tiling: CTA 128x128, 4 warps, warp tile 64x64, persistent CTAs
#define CTA_M     128
#define CTA_N     128
#define KC        64                        // K elems per chunk (128B rows)
#define ROW_B     128                       // bytes per smem row
#define NUM_IT    (IN_DIM / KC)             // 64
#define STAGES    3
#define XT_B      (CTA_M * ROW_B)           // 16384 (x tile, fp16 after convert)
#define WT_B      (CTA_N * ROW_B)           // 16384 (w tile)
#define STAGE_B   (XT_B + WT_B)             // 32768
#define SMEM_BYTES (STAGES * STAGE_B)       // 98304 per CTA -> 2 CTAs/SM
#define NTHREADS  128
#define N_TILES_N (OUT_DIM / CTA_N)         // 32
#define N_TILES   ((B_S / CTA_M) * N_TILES_N)  // 2048
#define GRID_SZ   296                       // 2 per SM, persistent

// ============================================================
// Scratch (device globals; no runtime allocation allowed)
// ============================================================
__device__ __align__(16) __half g_w[(size_t)OUT_DIM * IN_DIM];

// ============================================================
// PTX helpers (compute_100-safe: mma.sync / ldmatrix / cp.async only)
// ============================================================
static __device__ __forceinline__ void ldsm_x4(uint32_t* r, uint32_t addr) {
    asm volatile("ldmatrix.sync.aligned.m8n8.x4.shared.b16 {%0,%1,%2,%3}, [%4];"
        : "=r"(r[0]), "=r"(r[1]), "=r"(r[2]), "=r"(r[3]) : "r"(addr));
}

static __device__ __forceinline__ void mma16816(float* d, const uint32_t* a,
                                                const uint32_t* b) {
    asm volatile(
        "mma.sync.aligned.m16n8k16.row.col.f32.f16.f16.f32 "
        "{%0,%1,%2,%3}, {%4,%5,%6,%7}, {%8,%9}, {%0,%1,%2,%3};"
        : "+f"(d[0]), "+f"(d[1]), "+f"(d[2]), "+f"(d[3])
        : "r"(a[0]), "r"(a[1]), "r"(a[2]), "r"(a[3]), "r"(b[0]), "r"(b[1]));
}

#define CP_ASYNC16(dst, src) \
    asm volatile("cp.async.cg.shared.global [%0], [%1], 16;" :: "r"(dst), "l"(src))
#define CP_COMMIT() asm volatile("cp.async.commit_group;" ::: "memory")
#define CP_WAIT1()  asm volatile("cp.async.wait_group 1;" ::: "memory")

#define STS128(addr, p0, p1, p2, p3) \
    asm volatile("st.shared.v4.b32 [%0], {%1,%2,%3,%4};" \
        :: "r"(addr), "r"(p0), "r"(p1), "r"(p2), "r"(p3) : "memory")

// pack two fp32 into fp16x2 (lo = first arg)
static __device__ __forceinline__ uint32_t f22u(float lo, float hi) {
    __half2 h = __floats2half2_rn(lo, hi);
    return *reinterpret_cast<uint32_t*>(&h);
}

// swizzled byte offset within a tile: row r (128B rows), 16B chunk c (0..7)
static __device__ __forceinline__ uint32_t sw(uint32_t r, uint32_t c) {
    return r * ROW_B + ((c ^ (r & 7u)) << 4);
}

// ============================================================
// Prep (w only): dequantize codes -> fp16 g_w.
// Streaming reads (__ldcs): codes read exactly once.
// x conversion is fused into the GEMM mainloop.
// ============================================================
#define W_BLOCKS 4096
__global__ void __launch_bounds__(256)
prep_w_kernel(const int4* __restrict__ codes,
              const float* __restrict__ qgrid) {
    int base = blockIdx.x * 256 + threadIdx.x;
#pragma unroll
    for (int j = 0; j < 4; ++j) {
        int i = base + j * (W_BLOCKS * 256);
        int4 c = __ldcs(codes + i);
        int o = i >> 10;                  // (4*i) / 4096 : output row
        const float* g = qgrid + o * 8;   // GROUPS=1, GRID=8
        union U { __half h[4]; uint2 u; } H;
        H.h[0] = __float2half_rn(g[c.x]);
        H.h[1] = __float2half_rn(g[c.y]);
        H.h[2] = __float2half_rn(g[c.z]);
        H.h[3] = __float2half_rn(g[c.w]);
        reinterpret_cast<uint2*>(g_w)[i] = H.u;
    }
}

// ============================================================
// GEMM: out[8192,4096] = x @ w^T   (x fp32 converted in-kernel,
// w fp16 via cp.async, fp32 acc). Persistent CTAs (296 x ~7
// tiles). CTA 128x128, 4 warps, warp tile 64x64. 3-stage
// pipeline: w by cp.async, x by LDG.128(fp32)+cvt+STS.128 staged
// through the MMA shadow. At the legacy-HMMA roofline (~64%).
// ============================================================
__global__ void __launch_bounds__(NTHREADS, 2)
gemm_kernel(float* __restrict__ out, const float* __restrict__ X32)
{
    extern __shared__ char dsm[];
    const uint32_t smem = (uint32_t)__cvta_generic_to_shared(dsm);
    const int tid  = threadIdx.x;
    const int wid  = tid >> 5;
    const int lane = tid & 31;
    const int warp_m = wid >> 1;          // 0..1 -> M offset *64
    const int warp_n = wid & 1;           // 0..1 -> N offset *64

    // per-thread load geometry
    const uint32_t lr = (uint32_t)tid >> 3;        // base row 0..15
    const uint32_t lc = (uint32_t)tid & 7;         // 16B fp16-chunk col 0..7

    // w half-load h in {0,1}: rows [64h, 64h+64) (4 cp.async)
    auto load_w_half = [&](const __half* wb, uint32_t sb, int h) {
#pragma unroll
        for (int j = 0; j < 4; ++j) {
            uint32_t r = lr + 16 * (4 * h + j);
            CP_ASYNC16(sb + XT_B + sw(r, lc),
                reinterpret_cast<const char*>(wb + (size_t)r * IN_DIM) + lc * 16);
        }
    };

    // x fp32 chunk buffers (per-thread): 8 sub-chunks, <=4 live at once
    float4 xv[8][2];
    auto xldg = [&](const float* xb32, int j) {
        const float4* s = reinterpret_cast<const float4*>(
            xb32 + (size_t)(lr + 16u * j) * IN_DIM + lc * 8u);
        xv[j][0] = s[0];
        xv[j][1] = s[1];
    };
    auto xsts = [&](uint32_t sb, int j) {
        uint32_t p0 = f22u(xv[j][0].x, xv[j][0].y);
        uint32_t p1 = f22u(xv[j][0].z, xv[j][0].w);
        uint32_t p2 = f22u(xv[j][1].x, xv[j][1].y);
        uint32_t p3 = f22u(xv[j][1].z, xv[j][1].w);
        STS128(sb + sw(lr + 16u * j, lc), p0, p1, p2, p3);
    };

    // frag addressing
    const uint32_t lrow = lane & 15;
    const uint32_t lcol = lane >> 4;
    const uint32_t arow = warp_m * 64 + lrow;
    const uint32_t brow = warp_n * 64 + lrow;

    float acc[4][8][4];
    uint32_t Af[2][4][4];
    uint32_t Bf[2][8][2];

    auto load_frags = [&](uint32_t sb, int ks, int b) {
        const uint32_t cc = (uint32_t)(2 * ks) + lcol;
#pragma unroll
        for (int np = 0; np < 4; ++np) {
            uint32_t r4[4];
            ldsm_x4(r4, sb + XT_B + sw(brow + np * 16, cc));
            Bf[b][2 * np    ][0] = r4[0]; Bf[b][2 * np    ][1] = r4[2];
            Bf[b][2 * np + 1][0] = r4[1]; Bf[b][2 * np + 1][1] = r4[3];
        }
#pragma unroll
        for (int mt = 0; mt < 4; ++mt)
            ldsm_x4(Af[b][mt], sb + sw(arow + mt * 16, cc));
    };

    auto mma_burst = [&](int cur) {
#pragma unroll
        for (int mt = 0; mt < 4; ++mt)
#pragma unroll
            for (int nt = 0; nt < 8; ++nt)
                mma16816(acc[mt][nt], Af[cur][mt], Bf[cur][nt]);
    };

    // full chunk load (prologue only): x synchronous, w async + commit
    auto load_chunk_full = [&](int m0, int n0, int kit, int stg) {
        const float*  xb32 = X32 + (size_t)m0 * IN_DIM + kit * KC;
        const __half* wb   = g_w + (size_t)n0 * IN_DIM + kit * KC;
        const uint32_t sb  = smem + (uint32_t)stg * STAGE_B;
        load_w_half(wb, sb, 0);
        load_w_half(wb, sb, 1);
        CP_COMMIT();
#pragma unroll
        for (int j = 0; j < 8; ++j) { xldg(xb32, j); xsts(sb, j); }
    };

    // ---------------- persistent tile loop ----------------
    int tile = blockIdx.x;
    if (tile >= N_TILES) return;
    int m0 = (tile / N_TILES_N) * CTA_M;
    int n0 = (tile % N_TILES_N) * CTA_N;

    int ld_s = 0;                 // next stage to load into
    int co_s = 0;                 // next stage to consume
    load_chunk_full(m0, n0, 0, ld_s); ld_s = 1;
    load_chunk_full(m0, n0, 1, ld_s); ld_s = 2;

    while (true) {
        const int ntile = tile + GRID_SZ;
        const int nm0 = (ntile < N_TILES) ? (ntile / N_TILES_N) * CTA_M : 0;
        const int nn0 = (ntile < N_TILES) ? (ntile % N_TILES_N) * CTA_N : 0;

#pragma unroll
        for (int a = 0; a < 4; ++a)
#pragma unroll
            for (int b = 0; b < 8; ++b)
#pragma unroll
                for (int q = 0; q < 4; ++q) acc[a][b][q] = 0.f;

        for (int it = 0; it < NUM_IT; ++it) {
            CP_WAIT1();                    // w of chunk `it` landed
            __syncthreads();               // x STS of chunk `it` visible (done at it-2)

            // resolve lookahead sources for position it+2
            const float*  lxb32;
            const __half* lwb;
            bool has_load;
            if (it + 2 < NUM_IT) {
                lxb32 = X32 + (size_t)m0 * IN_DIM + (it + 2) * KC;
                lwb   = g_w + (size_t)n0 * IN_DIM + (it + 2) * KC;
                has_load = true;
            } else if (ntile < N_TILES) {
                lxb32 = X32 + (size_t)nm0 * IN_DIM + (it + 2 - NUM_IT) * KC;
                lwb   = g_w + (size_t)nn0 * IN_DIM + (it + 2 - NUM_IT) * KC;
                has_load = true;
            } else {
                lxb32 = X32; lwb = g_w;    // unused
                has_load = false;
            }
            const uint32_t lsb = smem + (uint32_t)ld_s * STAGE_B;
            const uint32_t sb  = smem + (uint32_t)co_s * STAGE_B;

            // ks=0
            load_frags(sb, 0, 0);
            load_frags(sb, 1, 1);
            if (has_load) {
                xldg(lxb32, 0); xldg(lxb32, 1); xldg(lxb32, 2); xldg(lxb32, 3);
                load_w_half(lwb, lsb, 0);
            }
            mma_burst(0);
            // ks=1
            load_frags(sb, 2, 0);
            if (has_load) {
                xsts(lsb, 0); xsts(lsb, 1);
                xldg(lxb32, 4); xldg(lxb32, 5);
            }
            mma_burst(1);
            // ks=2
            load_frags(sb, 3, 1);
            if (has_load) {
                xsts(lsb, 2); xsts(lsb, 3);
                xldg(lxb32, 6); xldg(lxb32, 7);
                load_w_half(lwb, lsb, 1);
            }
            mma_burst(0);
            // ks=3
            if (has_load) {
                xsts(lsb, 4); xsts(lsb, 5); xsts(lsb, 6); xsts(lsb, 7);
            }
            mma_burst(1);

            CP_COMMIT();                   // one w-group per iteration, always
            if (++ld_s == STAGES) ld_s = 0;
            if (++co_s == STAGES) co_s = 0;
        }

        // ------ epilogue: streaming stores (protect L2 for w + x fp32) ------
        {
            const int orow = m0 + warp_m * 64 + (lane >> 2);
            const int ocol = n0 + warp_n * 64 + (lane & 3) * 2;
#pragma unroll
            for (int mt = 0; mt < 4; ++mt)
#pragma unroll
                for (int nt = 0; nt < 8; ++nt) {
                    float* p0 = out + (size_t)(orow + mt * 16) * OUT_DIM + ocol + nt * 8;
                    float* p1 = out + (size_t)(orow + mt * 16 + 8) * OUT_DIM + ocol + nt * 8;
                    __stcs(reinterpret_cast<float2*>(p0),
                           make_float2(acc[mt][nt][0], acc[mt][nt][1]));
                    __stcs(reinterpret_cast<float2*>(p1),
                           make_float2(acc[mt][nt][2], acc[mt][nt][3]));
                }
        }

        if (ntile >= N_TILES) break;
        tile = ntile; m0 = nm0; n0 = nn0;
    }
}

// ============================================================
// Launch
// ============================================================
extern "C" void kernel_launch(void* const* d_in, const int* in_sizes, int n_in,
                              void* d_out, int out_size) {
    // Identify inputs by element count:
    //   x: 33554432 fp32, quant_grid: 32768 fp32, weight_codes: 16777216 int32
    const float* x = nullptr;
    const float* qgrid = nullptr;
    const int* codes = nullptr;
    for (int i = 0; i < n_in; ++i) {
        if (in_sizes[i] == 33554432)      x = (const float*)d_in[i];
        else if (in_sizes[i] == 32768)    qgrid = (const float*)d_in[i];
        else if (in_sizes[i] == 16777216) codes = (const int*)d_in[i];
    }
    float* out = (float*)d_out;

    prep_w_kernel<<<W_BLOCKS, 256>>>(
        reinterpret_cast<const int4*>(codes), qgrid);

    cudaFuncSetAttribute(gemm_kernel,
                         cudaFuncAttributeMaxDynamicSharedMemorySize, SMEM_BYTES);
    gemm_kernel<<<GRID_SZ, NTHREADS, SMEM_BYTES>>>(out, x);
}

// round 14
// speedup vs baseline: 1.6301x; 1.6301x over previous
#include <cuda_runtime.h>
#include <cuda_fp16.h>
#include <cstdint>

// ============================================================
// Problem sizes (fixed per reference)
// ============================================================
#define B_S       8192          // GEMM M  (B*S = 4*2048)
#define IN_DIM    4096          // K
#define OUT_DIM   4096          // N
// GEMM tiling: CTA 128x128, 4 warps, warp tile 64x64, persistent CTAs
#define CTA_M     128
#define CTA_N     128
#define KC        64                        // K elems per chunk (128B rows)
#define ROW_B     128                       // bytes per smem row
#define NUM_IT    (IN_DIM / KC)             // 64
#define STAGES    3
#define XT_B      (CTA_M * ROW_B)           // 16384 (x tile)
#define WT_B      (CTA_N * ROW_B)           // 16384 (w tile)
#define STAGE_B   (XT_B + WT_B)             // 32768
#define SMEM_BYTES (STAGES * STAGE_B)       // 98304 per CTA -> 2 CTAs/SM
#define NTHREADS  128
#define N_TILES_N (OUT_DIM / CTA_N)         // 32
#define N_TILES   ((B_S / CTA_M) * N_TILES_N)  // 2048
#define GRID_SZ   296                       // 2 per SM, persistent

// ============================================================
// Scratch (device globals; no runtime allocation allowed)
// ============================================================
__device__ __align__(16) __half g_x[(size_t)B_S * IN_DIM];
__device__ __align__(16) __half g_w[(size_t)OUT_DIM * IN_DIM];

// ============================================================
// PTX helpers (compute_100-safe: mma.sync / ldmatrix / cp.async only)
// ============================================================
static __device__ __forceinline__ void ldsm_x4(uint32_t* r, uint32_t addr) {
    asm volatile("ldmatrix.sync.aligned.m8n8.x4.shared.b16 {%0,%1,%2,%3}, [%4];"
        : "=r"(r[0]), "=r"(r[1]), "=r"(r[2]), "=r"(r[3]) : "r"(addr));
}

static __device__ __forceinline__ void mma16816(float* d, const uint32_t* a,
                                                const uint32_t* b) {
    asm volatile(
        "mma.sync.aligned.m16n8k16.row.col.f32.f16.f16.f32 "
        "{%0,%1,%2,%3}, {%4,%5,%6,%7}, {%8,%9}, {%0,%1,%2,%3};"
        : "+f"(d[0]), "+f"(d[1]), "+f"(d[2]), "+f"(d[3])
        : "r"(a[0]), "r"(a[1]), "r"(a[2]), "r"(a[3]), "r"(b[0]), "r"(b[1]));
}

#define CP_ASYNC16(dst, src) \
    asm volatile("cp.async.cg.shared.global [%0], [%1], 16;" :: "r"(dst), "l"(src))
#define CP_COMMIT() asm volatile("cp.async.commit_group;" ::: "memory")
#define CP_WAIT1()  asm volatile("cp.async.wait_group 1;" ::: "memory")

// swizzled byte offset within a tile: row r (128B rows), 16B chunk c (0..7)
static __device__ __forceinline__ uint32_t sw(uint32_t r, uint32_t c) {
    return r * ROW_B + ((c ^ (r & 7u)) << 4);
}

// ============================================================
// Fused prep: blocks [0, 8192) convert x fp32->fp16,
//             blocks [8192, 12288) dequantize w codes->fp16
// ============================================================
#define X_BLOCKS 8192
#define W_BLOCKS 4096
__global__ void prep_kernel(const float4* __restrict__ x,
                            const int4* __restrict__ codes,
                            const float* __restrict__ qgrid) {
    int b = blockIdx.x;
    if (b < X_BLOCKS) {
        int base = b * 256 + threadIdx.x;
#pragma unroll
        for (int j = 0; j < 4; ++j) {
            int i = base + j * (X_BLOCKS * 256);
            float4 v = x[i];
            union U { __half h[4]; uint2 u; } H;
            H.h[0] = __float2half_rn(v.x);
            H.h[1] = __float2half_rn(v.y);
            H.h[2] = __float2half_rn(v.z);
            H.h[3] = __float2half_rn(v.w);
            reinterpret_cast<uint2*>(g_x)[i] = H.u;
        }
    } else {
        int base = (b - X_BLOCKS) * 256 + threadIdx.x;
#pragma unroll
        for (int j = 0; j < 4; ++j) {
            int i = base + j * (W_BLOCKS * 256);
            int4 c = codes[i];
            int o = i >> 10;                  // (4*i) / 4096 : output row
            const float* g = qgrid + o * 8;   // GROUPS=1, GRID=8
            union U { __half h[4]; uint2 u; } H;
            H.h[0] = __float2half_rn(g[c.x]);
            H.h[1] = __float2half_rn(g[c.y]);
            H.h[2] = __float2half_rn(g[c.z]);
            H.h[3] = __float2half_rn(g[c.w]);
            reinterpret_cast<uint2*>(g_w)[i] = H.u;
        }
    }
}

// ============================================================
// GEMM: out[8192,4096] = x @ w^T   (fp16 in, fp32 acc)
// Persistent CTAs (296 x ~7 tiles). CTA 128x128, 4 warps, warp
// tile 64x64. Continuous 3-stage cp.async pipeline; the 16
// cp.async of each lookahead chunk are issued in two batches of
// 8 inside the MMA shadow (after ks=0 / ks=2 frag prefetch), one
// commit-group per iteration at the end.
// At the legacy-HMMA instruction-rate roofline (~64% tensor):
// HMMA.16816 accept rate ~1/12.5 cyc/SMSP is the hard ceiling
// on this compute_100 compile target (no tcgen05 available).
// ============================================================
__global__ void __launch_bounds__(NTHREADS, 2)
gemm_kernel(float* __restrict__ out)
{
    extern __shared__ char dsm[];
    const uint32_t smem = (uint32_t)__cvta_generic_to_shared(dsm);
    const int tid  = threadIdx.x;
    const int wid  = tid >> 5;
    const int lane = tid & 31;
    const int warp_m = wid >> 1;          // 0..1 -> M offset *64
    const int warp_n = wid & 1;           // 0..1 -> N offset *64

    // per-thread load geometry
    const uint32_t lr = (uint32_t)tid >> 3;        // base row 0..15
    const uint32_t lc = (uint32_t)tid & 7;         // 16B chunk col
    const uint32_t lcoff = lc * 16;                // byte offset along K

    // half-load h in {0,1}: rows [64h, 64h+64) of x and w tiles (8 cp.async)
    auto load_half = [&](const __half* xb, const __half* wb,
                         uint32_t sb, int h) {
#pragma unroll
        for (int j = 0; j < 4; ++j) {
            uint32_t r = lr + 16 * (4 * h + j);
            CP_ASYNC16(sb + sw(r, lc),
                reinterpret_cast<const char*>(xb + (size_t)r * IN_DIM) + lcoff);
        }
#pragma unroll
        for (int j = 0; j < 4; ++j) {
            uint32_t r = lr + 16 * (4 * h + j);
            CP_ASYNC16(sb + XT_B + sw(r, lc),
                reinterpret_cast<const char*>(wb + (size_t)r * IN_DIM) + lcoff);
        }
    };

    // frag addressing
    const uint32_t lrow = lane & 15;
    const uint32_t lcol = lane >> 4;
    const uint32_t arow = warp_m * 64 + lrow;
    const uint32_t brow = warp_n * 64 + lrow;

    float acc[4][8][4];
    uint32_t Af[2][4][4];
    uint32_t Bf[2][8][2];

    auto load_frags = [&](uint32_t sb, int ks, int b) {
        const uint32_t cc = (uint32_t)(2 * ks) + lcol;
#pragma unroll
        for (int np = 0; np < 4; ++np) {
            uint32_t r4[4];
            ldsm_x4(r4, sb + XT_B + sw(brow + np * 16, cc));
            Bf[b][2 * np    ][0] = r4[0]; Bf[b][2 * np    ][1] = r4[2];
            Bf[b][2 * np + 1][0] = r4[1]; Bf[b][2 * np + 1][1] = r4[3];
        }
#pragma unroll
        for (int mt = 0; mt < 4; ++mt)
            ldsm_x4(Af[b][mt], sb + sw(arow + mt * 16, cc));
    };

    auto mma_burst = [&](int cur) {
#pragma unroll
        for (int mt = 0; mt < 4; ++mt)
#pragma unroll
            for (int nt = 0; nt < 8; ++nt)
                mma16816(acc[mt][nt], Af[cur][mt], Bf[cur][nt]);
    };

    // full chunk load (prologue only)
    auto load_chunk_full = [&](int m0, int n0, int kit, int stg) {
        const __half* xb = g_x + (size_t)m0 * IN_DIM + kit * KC;
        const __half* wb = g_w + (size_t)n0 * IN_DIM + kit * KC;
        const uint32_t sb = smem + (uint32_t)stg * STAGE_B;
        load_half(xb, wb, sb, 0);
        load_half(xb, wb, sb, 1);
        CP_COMMIT();
    };

    // ---------------- persistent tile loop ----------------
    int tile = blockIdx.x;
    if (tile >= N_TILES) return;
    int m0 = (tile / N_TILES_N) * CTA_M;
    int n0 = (tile % N_TILES_N) * CTA_N;

    int ld_s = 0;                 // next stage to load into
    int co_s = 0;                 // next stage to consume
    load_chunk_full(m0, n0, 0, ld_s); ld_s = 1;
    load_chunk_full(m0, n0, 1, ld_s); ld_s = 2;

    while (true) {
        const int ntile = tile + GRID_SZ;
        const int nm0 = (ntile < N_TILES) ? (ntile / N_TILES_N) * CTA_M : 0;
        const int nn0 = (ntile < N_TILES) ? (ntile % N_TILES_N) * CTA_N : 0;

#pragma unroll
        for (int a = 0; a < 4; ++a)
#pragma unroll
            for (int b = 0; b < 8; ++b)
#pragma unroll
                for (int q = 0; q < 4; ++q) acc[a][b][q] = 0.f;

        for (int it = 0; it < NUM_IT; ++it) {
            CP_WAIT1();                    // chunk `it` landed
            __syncthreads();

            // resolve lookahead source for position it+2 before the burst loop
            const __half* lxb;
            const __half* lwb;
            bool has_load;
            if (it + 2 < NUM_IT) {
                lxb = g_x + (size_t)m0 * IN_DIM + (it + 2) * KC;
                lwb = g_w + (size_t)n0 * IN_DIM + (it + 2) * KC;
                has_load = true;
            } else if (ntile < N_TILES) {
                lxb = g_x + (size_t)nm0 * IN_DIM + (it + 2 - NUM_IT) * KC;
                lwb = g_w + (size_t)nn0 * IN_DIM + (it + 2 - NUM_IT) * KC;
                has_load = true;
            } else {
                lxb = g_x; lwb = g_w;      // unused
                has_load = false;
            }
            const uint32_t lsb = smem + (uint32_t)ld_s * STAGE_B;
            const uint32_t sb  = smem + (uint32_t)co_s * STAGE_B;

            // ks=0
            load_frags(sb, 0, 0);
            load_frags(sb, 1, 1);
            if (has_load) load_half(lxb, lwb, lsb, 0);
            mma_burst(0);
            // ks=1
            load_frags(sb, 2, 0);
            mma_burst(1);
            // ks=2
            load_frags(sb, 3, 1);
            if (has_load) load_half(lxb, lwb, lsb, 1);
            mma_burst(0);
            // ks=3
            mma_burst(1);

            CP_COMMIT();                   // one group per iteration, always
            if (++ld_s == STAGES) ld_s = 0;
            if (++co_s == STAGES) co_s = 0;
        }

        // ---------------- epilogue (next tile's loads already in flight) ----
        {
            const int orow = m0 + warp_m * 64 + (lane >> 2);
            const int ocol = n0 + warp_n * 64 + (lane & 3) * 2;
#pragma unroll
            for (int mt = 0; mt < 4; ++mt)
#pragma unroll
                for (int nt = 0; nt < 8; ++nt) {
                    float* p0 = out + (size_t)(orow + mt * 16) * OUT_DIM + ocol + nt * 8;
                    float* p1 = out + (size_t)(orow + mt * 16 + 8) * OUT_DIM + ocol + nt * 8;
                    *reinterpret_cast<float2*>(p0) =
                        make_float2(acc[mt][nt][0], acc[mt][nt][1]);
                    *reinterpret_cast<float2*>(p1) =
                        make_float2(acc[mt][nt][2], acc[mt][nt][3]);
                }
        }

        if (ntile >= N_TILES) break;
        tile = ntile; m0 = nm0; n0 = nn0;
    }
}

// ============================================================
// Launch
// ============================================================
extern "C" void kernel_launch(void* const* d_in, const int* in_sizes, int n_in,
                              void* d_out, int out_size) {
    // Identify inputs by element count:
    //   x: 33554432 fp32, quant_grid: 32768 fp32, weight_codes: 16777216 int32
    const float* x = nullptr;
    const float* qgrid = nullptr;
    const int* codes = nullptr;
    for (int i = 0; i < n_in; ++i) {
        if (in_sizes[i] == 33554432)      x = (const float*)d_in[i];
        else if (in_sizes[i] == 32768)    qgrid = (const float*)d_in[i];
        else if (in_sizes[i] == 16777216) codes = (const int*)d_in[i];
    }
    float* out = (float*)d_out;

    prep_kernel<<<X_BLOCKS + W_BLOCKS, 256>>>(
        reinterpret_cast<const float4*>(x),
        reinterpret_cast<const int4*>(codes), qgrid);

    cudaFuncSetAttribute(gemm_kernel,
                         cudaFuncAttributeMaxDynamicSharedMemorySize, SMEM_BYTES);
    gemm_kernel<<<GRID_SZ, NTHREADS, SMEM_BYTES>>>(out);
}

// round 15
// speedup vs baseline: 1.6342x; 1.0025x over previous
#include <cuda_runtime.h>
#include <cuda_fp16.h>
#include <cstdint>

// ============================================================
// Problem sizes (fixed per reference)
// ============================================================
#define B_S       8192          // GEMM M  (B*S = 4*2048)
#define IN_DIM    4096          // K
#define OUT_DIM   4096          // N
// GEMM tiling: CTA 128x128, 4 warps, warp tile 64x64, persistent CTAs
#define CTA_M     128
#define CTA_N     128
#define KC        64                        // K elems per chunk (128B rows)
#define ROW_B     128                       // bytes per smem row
#define NUM_IT    (IN_DIM / KC)             // 64
#define STAGES    3
#define XT_B      (CTA_M * ROW_B)           // 16384 (x tile)
#define WT_B      (CTA_N * ROW_B)           // 16384 (w tile)
#define STAGE_B   (XT_B + WT_B)             // 32768
#define SMEM_BYTES (STAGES * STAGE_B)       // 98304 per CTA -> 2 CTAs/SM
#define NTHREADS  128
#define N_TILES_N (OUT_DIM / CTA_N)         // 32
#define N_TILES   ((B_S / CTA_M) * N_TILES_N)  // 2048
#define GRID_SZ   296                       // 2 per SM, persistent

// ============================================================
// Scratch (device globals; no runtime allocation allowed)
// ============================================================
__device__ __align__(16) __half g_x[(size_t)B_S * IN_DIM];
__device__ __align__(16) __half g_w[(size_t)OUT_DIM * IN_DIM];

// ============================================================
// PTX helpers (compute_100-safe: mma.sync / ldmatrix / cp.async only)
// ============================================================
static __device__ __forceinline__ void ldsm_x4(uint32_t* r, uint32_t addr) {
    asm volatile("ldmatrix.sync.aligned.m8n8.x4.shared.b16 {%0,%1,%2,%3}, [%4];"
        : "=r"(r[0]), "=r"(r[1]), "=r"(r[2]), "=r"(r[3]) : "r"(addr));
}

static __device__ __forceinline__ void mma16816(float* d, const uint32_t* a,
                                                const uint32_t* b) {
    asm volatile(
        "mma.sync.aligned.m16n8k16.row.col.f32.f16.f16.f32 "
        "{%0,%1,%2,%3}, {%4,%5,%6,%7}, {%8,%9}, {%0,%1,%2,%3};"
        : "+f"(d[0]), "+f"(d[1]), "+f"(d[2]), "+f"(d[3])
        : "r"(a[0]), "r"(a[1]), "r"(a[2]), "r"(a[3]), "r"(b[0]), "r"(b[1]));
}

#define CP_ASYNC16(dst, src) \
    asm volatile("cp.async.cg.shared.global [%0], [%1], 16;" :: "r"(dst), "l"(src))
#define CP_COMMIT() asm volatile("cp.async.commit_group;" ::: "memory")
#define CP_WAIT1()  asm volatile("cp.async.wait_group 1;" ::: "memory")

// swizzled byte offset within a tile: row r (128B rows), 16B chunk c (0..7)
static __device__ __forceinline__ uint32_t sw(uint32_t r, uint32_t c) {
    return r * ROW_B + ((c ^ (r & 7u)) << 4);
}

// ============================================================
// Fused prep: blocks [0, 8192) convert x fp32->fp16,
//             blocks [8192, 12288) dequantize w codes->fp16
// ============================================================
#define X_BLOCKS 8192
#define W_BLOCKS 4096
__global__ void prep_kernel(const float4* __restrict__ x,
                            const int4* __restrict__ codes,
                            const float* __restrict__ qgrid) {
    int b = blockIdx.x;
    if (b < X_BLOCKS) {
        int base = b * 256 + threadIdx.x;
#pragma unroll
        for (int j = 0; j < 4; ++j) {
            int i = base + j * (X_BLOCKS * 256);
            float4 v = x[i];
            union U { __half h[4]; uint2 u; } H;
            H.h[0] = __float2half_rn(v.x);
            H.h[1] = __float2half_rn(v.y);
            H.h[2] = __float2half_rn(v.z);
            H.h[3] = __float2half_rn(v.w);
            reinterpret_cast<uint2*>(g_x)[i] = H.u;
        }
    } else {
        int base = (b - X_BLOCKS) * 256 + threadIdx.x;
#pragma unroll
        for (int j = 0; j < 4; ++j) {
            int i = base + j * (W_BLOCKS * 256);
            int4 c = codes[i];
            int o = i >> 10;                  // (4*i) / 4096 : output row
            const float* g = qgrid + o * 8;   // GROUPS=1, GRID=8
            union U { __half h[4]; uint2 u; } H;
            H.h[0] = __float2half_rn(g[c.x]);
            H.h[1] = __float2half_rn(g[c.y]);
            H.h[2] = __float2half_rn(g[c.z]);
            H.h[3] = __float2half_rn(g[c.w]);
            reinterpret_cast<uint2*>(g_w)[i] = H.u;
        }
    }
}

// ============================================================
// GEMM: out[8192,4096] = x @ w^T   (fp16 in, fp32 acc)
// Persistent CTAs (296 x ~7 tiles). CTA 128x128, 4 warps, warp
// tile 64x64. Continuous 3-stage cp.async pipeline; the 16
// cp.async of each lookahead chunk are issued in two batches of
// 8 inside the MMA shadow (after ks=0 / ks=2 frag prefetch), one
// commit-group per iteration at the end.
// At the legacy-HMMA instruction-rate roofline (~64% tensor):
// HMMA.16816 accept rate ~1/12.5 cyc/SMSP is the hard ceiling
// on this compute_100 compile target (no tcgen05 available).
// Verified schedule-invariant across 7 kernel variants (R4-R14).
// ============================================================
__global__ void __launch_bounds__(NTHREADS, 2)
gemm_kernel(float* __restrict__ out)
{
    extern __shared__ char dsm[];
    const uint32_t smem = (uint32_t)__cvta_generic_to_shared(dsm);
    const int tid  = threadIdx.x;
    const int wid  = tid >> 5;
    const int lane = tid & 31;
    const int warp_m = wid >> 1;          // 0..1 -> M offset *64
    const int warp_n = wid & 1;           // 0..1 -> N offset *64

    // per-thread load geometry
    const uint32_t lr = (uint32_t)tid >> 3;        // base row 0..15
    const uint32_t lc = (uint32_t)tid & 7;         // 16B chunk col
    const uint32_t lcoff = lc * 16;                // byte offset along K

    // half-load h in {0,1}: rows [64h, 64h+64) of x and w tiles (8 cp.async)
    auto load_half = [&](const __half* xb, const __half* wb,
                         uint32_t sb, int h) {
#pragma unroll
        for (int j = 0; j < 4; ++j) {
            uint32_t r = lr + 16 * (4 * h + j);
            CP_ASYNC16(sb + sw(r, lc),
                reinterpret_cast<const char*>(xb + (size_t)r * IN_DIM) + lcoff);
        }
#pragma unroll
        for (int j = 0; j < 4; ++j) {
            uint32_t r = lr + 16 * (4 * h + j);
            CP_ASYNC16(sb + XT_B + sw(r, lc),
                reinterpret_cast<const char*>(wb + (size_t)r * IN_DIM) + lcoff);
        }
    };

    // frag addressing
    const uint32_t lrow = lane & 15;
    const uint32_t lcol = lane >> 4;
    const uint32_t arow = warp_m * 64 + lrow;
    const uint32_t brow = warp_n * 64 + lrow;

    float acc[4][8][4];
    uint32_t Af[2][4][4];
    uint32_t Bf[2][8][2];

    auto load_frags = [&](uint32_t sb, int ks, int b) {
        const uint32_t cc = (uint32_t)(2 * ks) + lcol;
#pragma unroll
        for (int np = 0; np < 4; ++np) {
            uint32_t r4[4];
            ldsm_x4(r4, sb + XT_B + sw(brow + np * 16, cc));
            Bf[b][2 * np    ][0] = r4[0]; Bf[b][2 * np    ][1] = r4[2];
            Bf[b][2 * np + 1][0] = r4[1]; Bf[b][2 * np + 1][1] = r4[3];
        }
#pragma unroll
        for (int mt = 0; mt < 4; ++mt)
            ldsm_x4(Af[b][mt], sb + sw(arow + mt * 16, cc));
    };

    auto mma_burst = [&](int cur) {
#pragma unroll
        for (int mt = 0; mt < 4; ++mt)
#pragma unroll
            for (int nt = 0; nt < 8; ++nt)
                mma16816(acc[mt][nt], Af[cur][mt], Bf[cur][nt]);
    };

    // full chunk load (prologue only)
    auto load_chunk_full = [&](int m0, int n0, int kit, int stg) {
        const __half* xb = g_x + (size_t)m0 * IN_DIM + kit * KC;
        const __half* wb = g_w + (size_t)n0 * IN_DIM + kit * KC;
        const uint32_t sb = smem + (uint32_t)stg * STAGE_B;
        load_half(xb, wb, sb, 0);
        load_half(xb, wb, sb, 1);
        CP_COMMIT();
    };

    // ---------------- persistent tile loop ----------------
    int tile = blockIdx.x;
    if (tile >= N_TILES) return;
    int m0 = (tile / N_TILES_N) * CTA_M;
    int n0 = (tile % N_TILES_N) * CTA_N;

    int ld_s = 0;                 // next stage to load into
    int co_s = 0;                 // next stage to consume
    load_chunk_full(m0, n0, 0, ld_s); ld_s = 1;
    load_chunk_full(m0, n0, 1, ld_s); ld_s = 2;

    while (true) {
        const int ntile = tile + GRID_SZ;
        const int nm0 = (ntile < N_TILES) ? (ntile / N_TILES_N) * CTA_M : 0;
        const int nn0 = (ntile < N_TILES) ? (ntile % N_TILES_N) * CTA_N : 0;

#pragma unroll
        for (int a = 0; a < 4; ++a)
#pragma unroll
            for (int b = 0; b < 8; ++b)
#pragma unroll
                for (int q = 0; q < 4; ++q) acc[a][b][q] = 0.f;

        for (int it = 0; it < NUM_IT; ++it) {
            CP_WAIT1();                    // chunk `it` landed
            __syncthreads();

            // resolve lookahead source for position it+2 before the burst loop
            const __half* lxb;
            const __half* lwb;
            bool has_load;
            if (it + 2 < NUM_IT) {
                lxb = g_x + (size_t)m0 * IN_DIM + (it + 2) * KC;
                lwb = g_w + (size_t)n0 * IN_DIM + (it + 2) * KC;
                has_load = true;
            } else if (ntile < N_TILES) {
                lxb = g_x + (size_t)nm0 * IN_DIM + (it + 2 - NUM_IT) * KC;
                lwb = g_w + (size_t)nn0 * IN_DIM + (it + 2 - NUM_IT) * KC;
                has_load = true;
            } else {
                lxb = g_x; lwb = g_w;      // unused
                has_load = false;
            }
            const uint32_t lsb = smem + (uint32_t)ld_s * STAGE_B;
            const uint32_t sb  = smem + (uint32_t)co_s * STAGE_B;

            // ks=0
            load_frags(sb, 0, 0);
            load_frags(sb, 1, 1);
            if (has_load) load_half(lxb, lwb, lsb, 0);
            mma_burst(0);
            // ks=1
            load_frags(sb, 2, 0);
            mma_burst(1);
            // ks=2
            load_frags(sb, 3, 1);
            if (has_load) load_half(lxb, lwb, lsb, 1);
            mma_burst(0);
            // ks=3
            mma_burst(1);

            CP_COMMIT();                   // one group per iteration, always
            if (++ld_s == STAGES) ld_s = 0;
            if (++co_s == STAGES) co_s = 0;
        }

        // ---------------- epilogue (next tile's loads already in flight) ----
        {
            const int orow = m0 + warp_m * 64 + (lane >> 2);
            const int ocol = n0 + warp_n * 64 + (lane & 3) * 2;
#pragma unroll
            for (int mt = 0; mt < 4; ++mt)
#pragma unroll
                for (int nt = 0; nt < 8; ++nt) {
                    float* p0 = out + (size_t)(orow + mt * 16) * OUT_DIM + ocol + nt * 8;
                    float* p1 = out + (size_t)(orow + mt * 16 + 8) * OUT_DIM + ocol + nt * 8;
                    *reinterpret_cast<float2*>(p0) =
                        make_float2(acc[mt][nt][0], acc[mt][nt][1]);
                    *reinterpret_cast<float2*>(p1) =
                        make_float2(acc[mt][nt][2], acc[mt][nt][3]);
                }
        }

        if (ntile >= N_TILES) break;
        tile = ntile; m0 = nm0; n0 = nn0;
    }
}

// ============================================================
// Launch
// ============================================================
extern "C" void kernel_launch(void* const* d_in, const int* in_sizes, int n_in,
                              void* d_out, int out_size) {
    // Identify inputs by element count:
    //   x: 33554432 fp32, quant_grid: 32768 fp32, weight_codes: 16777216 int32
    const float* x = nullptr;
    const float* qgrid = nullptr;
    const int* codes = nullptr;
    for (int i = 0; i < n_in; ++i) {
        if (in_sizes[i] == 33554432)      x = (const float*)d_in[i];
        else if (in_sizes[i] == 32768)    qgrid = (const float*)d_in[i];
        else if (in_sizes[i] == 16777216) codes = (const int*)d_in[i];
    }
    float* out = (float*)d_out;

    prep_kernel<<<X_BLOCKS + W_BLOCKS, 256>>>(
        reinterpret_cast<const float4*>(x),
        reinterpret_cast<const int4*>(codes), qgrid);

    cudaFuncSetAttribute(gemm_kernel,
                         cudaFuncAttributeMaxDynamicSharedMemorySize, SMEM_BYTES);
    gemm_kernel<<<GRID_SZ, NTHREADS, SMEM_BYTES>>>(out);
}